// round 5
// baseline (speedup 1.0000x reference)
#include <cuda_runtime.h>
#include <cstdint>

#define NV      500000
#define KK      27
#define MT      128          // rows per conv block
#define A_ST    68           // A smem row stride (floats): 68*4 B, 16B-aligned rows, conflict-free
#define W_ST    72           // W smem row stride (floats): 72 mod 32 = 8 -> conflict-free B-frag reads
#define SMEM_BYTES ((MT * A_ST + 64 * W_ST) * 4)

// ---- scratch (static device globals: allocation-free per harness rules) ----
__device__ float g_y1[(size_t)NV * 64];   // 128 MB intermediate
__device__ float g_partials[512 * 128];   // per-block BN partial sums / sumsq
__device__ float g_ss1[128];              // conv1 BN: scale[0:64], shift[64:128]
__device__ float g_ss2[128];              // conv2 BN

__device__ __forceinline__ unsigned f2tf(float f) {
    unsigned u;
    asm("cvt.rna.tf32.f32 %0, %1;" : "=r"(u) : "f"(f));
    return u;
}

// ============================================================================
// Gather-GEMM submanifold conv: y[n,:] = sum_k valid[k,n] * x[nbr[k,n],:] @ W[k]
// Block: 256 threads (8 warps), tile 128 rows x 64 cols, fp32 accum in regs,
// tf32 mma.sync m16n8k8.
// ============================================================================
__global__ __launch_bounds__(256) void conv_kernel(
    const float* __restrict__ x, const int* __restrict__ nbr,
    const float* __restrict__ valid, const float* __restrict__ W,
    float* __restrict__ y)
{
    extern __shared__ unsigned smem[];
    unsigned* As = smem;                    // [MT][A_ST] tf32 bits
    unsigned* Bs = smem + MT * A_ST;        // [64][W_ST] tf32 bits

    const int tid  = threadIdx.x;
    const int warp = tid >> 5, lane = tid & 31;
    const int g    = lane >> 2, tig = lane & 3;   // groupID / thread-in-group
    const int rowBase = blockIdx.x * MT;
    const int arow  = tid & 127;            // gather: one row per thread-pair
    const int ahalf = tid >> 7;             // which 32-col half this thread fills
    const int grow  = rowBase + arow;
    const int m0    = warp * 16;            // this warp's 16-row slice

    float acc[8][4];
#pragma unroll
    for (int n = 0; n < 8; ++n)
#pragma unroll
        for (int j = 0; j < 4; ++j) acc[n][j] = 0.f;

    for (int k = 0; k < KK; ++k) {
        // ---- gather A tile (masked), pre-rounded to tf32 ----
        int idx = 0; float v = 0.f;
        if (grow < NV) {
            idx = nbr[(size_t)k * NV + grow];
            v   = valid[(size_t)k * NV + grow];
        }
        const float4* src  = reinterpret_cast<const float4*>(x + (size_t)idx * 64) + ahalf * 8;
        unsigned*     adst = As + arow * A_ST + ahalf * 32;
#pragma unroll
        for (int i = 0; i < 8; ++i) {
            float4 t = src[i];
            uint4 p;
            p.x = f2tf(t.x * v); p.y = f2tf(t.y * v);
            p.z = f2tf(t.z * v); p.w = f2tf(t.w * v);
            *reinterpret_cast<uint4*>(adst + i * 4) = p;   // 16B-aligned, conflict-free
        }
        // ---- stage W[k] (64x64) ----
        const float4* wsrc = reinterpret_cast<const float4*>(W + (size_t)k * 4096);
#pragma unroll
        for (int i = 0; i < 4; ++i) {
            int q = tid + 256 * i;               // 0..1023 float4s
            float4 t = wsrc[q];
            uint4 p;
            p.x = f2tf(t.x); p.y = f2tf(t.y); p.z = f2tf(t.z); p.w = f2tf(t.w);
            *reinterpret_cast<uint4*>(Bs + (q >> 4) * W_ST + (q & 15) * 4) = p;
        }
        __syncthreads();

        // ---- 8 k-chunks x 8 n-tiles of m16n8k8 tf32 mma ----
#pragma unroll
        for (int kc = 0; kc < 8; ++kc) {
            unsigned a0 = As[(m0 + g)     * A_ST + kc * 8 + tig];
            unsigned a1 = As[(m0 + g + 8) * A_ST + kc * 8 + tig];
            unsigned a2 = As[(m0 + g)     * A_ST + kc * 8 + tig + 4];
            unsigned a3 = As[(m0 + g + 8) * A_ST + kc * 8 + tig + 4];
#pragma unroll
            for (int n = 0; n < 8; ++n) {
                unsigned b0 = Bs[(kc * 8 + tig)     * W_ST + n * 8 + g];
                unsigned b1 = Bs[(kc * 8 + tig + 4) * W_ST + n * 8 + g];
                asm volatile(
                    "mma.sync.aligned.m16n8k8.row.col.f32.tf32.tf32.f32 "
                    "{%0,%1,%2,%3},{%4,%5,%6,%7},{%8,%9},{%0,%1,%2,%3};\n"
                    : "+f"(acc[n][0]), "+f"(acc[n][1]), "+f"(acc[n][2]), "+f"(acc[n][3])
                    : "r"(a0), "r"(a1), "r"(a2), "r"(a3), "r"(b0), "r"(b1));
            }
        }
        __syncthreads();
    }

    // ---- epilogue: fragment layout c{0,1}->rows g, c{2,3}->rows g+8 ----
    const int r0 = rowBase + m0 + g;
    const int r1 = r0 + 8;
#pragma unroll
    for (int n = 0; n < 8; ++n) {
        int col = n * 8 + 2 * tig;
        if (r0 < NV)
            *reinterpret_cast<float2*>(y + (size_t)r0 * 64 + col) = make_float2(acc[n][0], acc[n][1]);
        if (r1 < NV)
            *reinterpret_cast<float2*>(y + (size_t)r1 * 64 + col) = make_float2(acc[n][2], acc[n][3]);
    }
}

// ============================================================================
// BN statistics: deterministic two-stage reduction (no float atomics)
// ============================================================================
__global__ __launch_bounds__(256) void stats_kernel(
    const float* __restrict__ y, float* __restrict__ partials)
{
    const int tid = threadIdx.x;
    const int c = tid & 63, r = tid >> 6;
    float s = 0.f, q = 0.f;
    for (int row = blockIdx.x * 4 + r; row < NV; row += 2048) {
        float v = y[(size_t)row * 64 + c];
        s += v; q += v * v;
    }
    __shared__ float sh[512];
    sh[tid] = s; sh[256 + tid] = q;
    __syncthreads();
    if (tid < 64) {
        float ts = sh[tid] + sh[tid + 64] + sh[tid + 128] + sh[tid + 192];
        float tq = sh[256 + tid] + sh[256 + tid + 64] + sh[256 + tid + 128] + sh[256 + tid + 192];
        partials[blockIdx.x * 128 + tid]      = ts;
        partials[blockIdx.x * 128 + 64 + tid] = tq;
    }
}

__global__ void finalize_stats_kernel(
    const float* __restrict__ partials, const float* __restrict__ gamma,
    const float* __restrict__ beta, float* __restrict__ ss)
{
    const int c = threadIdx.x;   // 0..63
    float s = 0.f, q = 0.f;
    for (int b = 0; b < 512; ++b) {
        s += partials[b * 128 + c];
        q += partials[b * 128 + 64 + c];
    }
    const float invN = 1.0f / (float)NV;
    float mean  = s * invN;
    float var   = q * invN - mean * mean;
    float scale = gamma[c] * rsqrtf(var + 1e-5f);
    ss[c]      = scale;
    ss[64 + c] = beta[c] - mean * scale;
}

// ============================================================================
// Fused BN (+optional residual) + ReLU, vectorized float4, in place
// ============================================================================
__global__ __launch_bounds__(256) void bn_act_kernel(
    float* __restrict__ y, const float* __restrict__ ss,
    const float* __restrict__ residual)
{
    long i = (long)blockIdx.x * blockDim.x + threadIdx.x;
    if (i >= (long)NV * 16) return;            // NV*64/4 float4s
    float4 v = reinterpret_cast<float4*>(y)[i];
    const int cb = (int)(i & 15);              // channel-group (4 channels)
    float4 sc = reinterpret_cast<const float4*>(ss)[cb];
    float4 sh = reinterpret_cast<const float4*>(ss + 64)[cb];
    float4 r;
    r.x = fmaf(v.x, sc.x, sh.x);
    r.y = fmaf(v.y, sc.y, sh.y);
    r.z = fmaf(v.z, sc.z, sh.z);
    r.w = fmaf(v.w, sc.w, sh.w);
    if (residual) {
        float4 f = reinterpret_cast<const float4*>(residual)[i];
        r.x += f.x; r.y += f.y; r.z += f.z; r.w += f.w;
    }
    r.x = fmaxf(r.x, 0.f); r.y = fmaxf(r.y, 0.f);
    r.z = fmaxf(r.z, 0.f); r.w = fmaxf(r.w, 0.f);
    reinterpret_cast<float4*>(y)[i] = r;
}

// ============================================================================
// kernel_launch: conv1 -> stats1 -> bn+relu (in place) -> conv2 -> stats2
//                -> bn + residual + relu  (all graph-capturable launches)
// ============================================================================
extern "C" void kernel_launch(void* const* d_in, const int* in_sizes, int n_in,
                              void* d_out, int out_size)
{
    const float* features = (const float*)d_in[0];
    const int*   nbr      = (const int*)  d_in[1];
    const float* valid    = (const float*)d_in[2];
    const float* W1       = (const float*)d_in[3];
    const float* gamma1   = (const float*)d_in[4];
    const float* beta1    = (const float*)d_in[5];
    const float* W2       = (const float*)d_in[6];
    const float* gamma2   = (const float*)d_in[7];
    const float* beta2    = (const float*)d_in[8];
    float* out = (float*)d_out;

    float *y1, *partials, *ss1, *ss2;
    cudaGetSymbolAddress((void**)&y1,       g_y1);
    cudaGetSymbolAddress((void**)&partials, g_partials);
    cudaGetSymbolAddress((void**)&ss1,      g_ss1);
    cudaGetSymbolAddress((void**)&ss2,      g_ss2);

    cudaFuncSetAttribute(conv_kernel, cudaFuncAttributeMaxDynamicSharedMemorySize, SMEM_BYTES);

    const int convBlocks = (NV + MT - 1) / MT;     // 3907
    const int ewBlocks   = ((long)NV * 16 + 255) / 256;

    conv_kernel<<<convBlocks, 256, SMEM_BYTES>>>(features, nbr, valid, W1, y1);
    stats_kernel<<<512, 256>>>(y1, partials);
    finalize_stats_kernel<<<1, 64>>>(partials, gamma1, beta1, ss1);
    bn_act_kernel<<<ewBlocks, 256>>>(y1, ss1, nullptr);

    conv_kernel<<<convBlocks, 256, SMEM_BYTES>>>(y1, nbr, valid, W2, out);
    stats_kernel<<<512, 256>>>(out, partials);
    finalize_stats_kernel<<<1, 64>>>(partials, gamma2, beta2, ss2);
    bn_act_kernel<<<ewBlocks, 256>>>(out, ss2, features);
}

// round 6
// speedup vs baseline: 1.4390x; 1.4390x over previous
#include <cuda_runtime.h>
#include <cuda_fp16.h>
#include <cstdint>

#define NV      500000
#define KK      27
#define MT      128           // rows per conv block tile
#define AST     72            // A smem row stride in halves (144 B, conflict-free)
#define BST     72            // W smem row stride in halves
#define A_BUF_HALVES (MT * AST)        // 9216 halves = 18432 B
#define B_BUF_HALVES (64 * BST)        // 4608 halves = 9216 B
#define SMEM_BYTES ((2 * A_BUF_HALVES + 2 * B_BUF_HALVES) * 2)   // 55296 B

// ---- scratch (static device globals: allocation-free per harness rules) ----
__device__ __half g_xh[(size_t)NV * 64];      // 64 MB: features in fp16
__device__ __half g_y1h[(size_t)NV * 64];     // 64 MB: conv1 output / conv2 input
__device__ __half g_Wt[2][KK * 64 * 64];      // transposed fp16 weights [k][cout][cin]
__device__ float  g_partials[512 * 128];      // BN partial sums / sumsq
__device__ float  g_ss1[128];                 // BN1 scale[0:64], shift[64:128]
__device__ float  g_ss2[128];                 // BN2

// ============================================================================
// Gather-GEMM submanifold conv, fp16 inputs, fp32 accum, fp16 m16n8k16 mma.
// Block: 256 threads (8 warps), tile 128 rows x 64 cols.
// Double-buffered A & W in smem, one __syncthreads per k-offset.
// Invalid neighbor rows are zero-filled with NO global load.
// ============================================================================
template <typename OutT>
__global__ __launch_bounds__(256) void conv_kernel(
    const __half* __restrict__ x, const int* __restrict__ nbr,
    const float* __restrict__ valid, const __half* __restrict__ Wt,
    OutT* __restrict__ y)
{
    extern __shared__ __align__(16) __half smem[];
    __half* As = smem;                               // 2 x [MT][AST]
    __half* Bs = smem + 2 * A_BUF_HALVES;            // 2 x [64][BST]

    const int tid  = threadIdx.x;
    const int warp = tid >> 5, lane = tid & 31;
    const int g    = lane >> 2, tig = lane & 3;      // groupID / thread-in-group
    const int rowBase = blockIdx.x * MT;
    const int arow  = tid & 127;                     // gather row within tile
    const int ahalf = tid >> 7;                      // which 64B half-row
    const int grow  = rowBase + arow;
    const int m0    = warp * 16;

    float acc[8][4];
#pragma unroll
    for (int n = 0; n < 8; ++n)
#pragma unroll
        for (int j = 0; j < 4; ++j) acc[n][j] = 0.f;

    uint4 aregs[4];
    uint4 wregs[2];

    // ---- prefetch stage 0 ----
    {
        bool vld = false; int idx = 0;
        if (grow < NV && valid[grow] > 0.5f) { vld = true; idx = nbr[grow]; }
#pragma unroll
        for (int i = 0; i < 4; ++i) aregs[i] = make_uint4(0, 0, 0, 0);
        if (vld) {
            const uint4* src = reinterpret_cast<const uint4*>(x + (size_t)idx * 64) + ahalf * 4;
#pragma unroll
            for (int i = 0; i < 4; ++i) aregs[i] = src[i];
        }
        const uint4* wsrc = reinterpret_cast<const uint4*>(Wt);
        wregs[0] = wsrc[tid];
        wregs[1] = wsrc[tid + 256];
    }

    for (int k = 0; k < KK; ++k) {
        const int buf = k & 1;
        // ---- store staged tiles ----
        {
            __half* adst = As + buf * A_BUF_HALVES + arow * AST + ahalf * 32;
#pragma unroll
            for (int i = 0; i < 4; ++i)
                *reinterpret_cast<uint4*>(adst + i * 8) = aregs[i];
            __half* bbase = Bs + buf * B_BUF_HALVES;
#pragma unroll
            for (int i = 0; i < 2; ++i) {
                int q = tid + 256 * i;                 // 0..511 uint4s, 8 per row
                *reinterpret_cast<uint4*>(bbase + (q >> 3) * BST + (q & 7) * 8) = wregs[i];
            }
        }
        __syncthreads();

        // ---- prefetch stage k+1 (overlaps with MMA below) ----
        if (k + 1 < KK) {
            bool vld = false; int idx = 0;
            if (grow < NV && valid[(size_t)(k + 1) * NV + grow] > 0.5f) {
                vld = true; idx = nbr[(size_t)(k + 1) * NV + grow];
            }
#pragma unroll
            for (int i = 0; i < 4; ++i) aregs[i] = make_uint4(0, 0, 0, 0);
            if (vld) {
                const uint4* src = reinterpret_cast<const uint4*>(x + (size_t)idx * 64) + ahalf * 4;
#pragma unroll
                for (int i = 0; i < 4; ++i) aregs[i] = src[i];
            }
            const uint4* wsrc = reinterpret_cast<const uint4*>(Wt + (size_t)(k + 1) * 4096);
            wregs[0] = wsrc[tid];
            wregs[1] = wsrc[tid + 256];
        }

        // ---- MMA: 4 k-chunks (K=16) x 8 n-tiles of m16n8k16 f16 ----
        const __half* A = As + buf * A_BUF_HALVES;
        const __half* B = Bs + buf * B_BUF_HALVES;
#pragma unroll
        for (int kc = 0; kc < 4; ++kc) {
            unsigned a0 = *reinterpret_cast<const unsigned*>(A + (m0 + g)     * AST + kc * 16 + 2 * tig);
            unsigned a1 = *reinterpret_cast<const unsigned*>(A + (m0 + g + 8) * AST + kc * 16 + 2 * tig);
            unsigned a2 = *reinterpret_cast<const unsigned*>(A + (m0 + g)     * AST + kc * 16 + 2 * tig + 8);
            unsigned a3 = *reinterpret_cast<const unsigned*>(A + (m0 + g + 8) * AST + kc * 16 + 2 * tig + 8);
#pragma unroll
            for (int n = 0; n < 8; ++n) {
                unsigned b0 = *reinterpret_cast<const unsigned*>(B + (n * 8 + g) * BST + kc * 16 + 2 * tig);
                unsigned b1 = *reinterpret_cast<const unsigned*>(B + (n * 8 + g) * BST + kc * 16 + 2 * tig + 8);
                asm volatile(
                    "mma.sync.aligned.m16n8k16.row.col.f32.f16.f16.f32 "
                    "{%0,%1,%2,%3},{%4,%5,%6,%7},{%8,%9},{%0,%1,%2,%3};\n"
                    : "+f"(acc[n][0]), "+f"(acc[n][1]), "+f"(acc[n][2]), "+f"(acc[n][3])
                    : "r"(a0), "r"(a1), "r"(a2), "r"(a3), "r"(b0), "r"(b1));
            }
        }
        // no trailing sync: next iteration writes the other buffer; its
        // __syncthreads separates this MMA from the k+2 overwrite.
    }

    // ---- epilogue: c{0,1}->row g, c{2,3}->row g+8 ----
    const int r0 = rowBase + m0 + g;
    const int r1 = r0 + 8;
#pragma unroll
    for (int n = 0; n < 8; ++n) {
        int col = n * 8 + 2 * tig;
        if constexpr (sizeof(OutT) == 4) {
            if (r0 < NV)
                *reinterpret_cast<float2*>((float*)y + (size_t)r0 * 64 + col) = make_float2(acc[n][0], acc[n][1]);
            if (r1 < NV)
                *reinterpret_cast<float2*>((float*)y + (size_t)r1 * 64 + col) = make_float2(acc[n][2], acc[n][3]);
        } else {
            if (r0 < NV)
                *reinterpret_cast<__half2*>((__half*)y + (size_t)r0 * 64 + col) = __floats2half2_rn(acc[n][0], acc[n][1]);
            if (r1 < NV)
                *reinterpret_cast<__half2*>((__half*)y + (size_t)r1 * 64 + col) = __floats2half2_rn(acc[n][2], acc[n][3]);
        }
    }
}

// ============================================================================
// One-shot converters
// ============================================================================
__global__ __launch_bounds__(256) void cvt_features_kernel(
    const float4* __restrict__ x, __half2* __restrict__ xh)
{
    long i = (long)blockIdx.x * 256 + threadIdx.x;   // over NV*16 float4s
    float4 v = x[i];
    xh[2 * i]     = __floats2half2_rn(v.x, v.y);
    xh[2 * i + 1] = __floats2half2_rn(v.z, v.w);
}

__global__ void cvt_weights_kernel(
    const float* __restrict__ W1, const float* __restrict__ W2,
    __half* __restrict__ Wt)   // [2][27][cout][cin]
{
    int o = blockIdx.x * 256 + threadIdx.x;
    if (o >= 2 * KK * 4096) return;
    int wsel = o / (KK * 4096);
    int rem  = o % (KK * 4096);
    int k  = rem >> 12;
    int t  = rem & 4095;
    int co = t >> 6, ci = t & 63;
    const float* W = wsel ? W2 : W1;
    Wt[o] = __float2half_rn(W[(size_t)k * 4096 + ci * 64 + co]);
}

// ============================================================================
// BN statistics: deterministic two-stage reduction (no float atomics)
// ============================================================================
__global__ __launch_bounds__(256) void stats_half_kernel(
    const __half2* __restrict__ y, float* __restrict__ partials)
{
    const int tid = threadIdx.x;
    const int c2 = tid & 31, r = tid >> 5;           // half2-lane / row group
    float s0 = 0.f, q0 = 0.f, s1 = 0.f, q1 = 0.f;
    for (int row = blockIdx.x * 8 + r; row < NV; row += 4096) {
        float2 f = __half22float2(y[(size_t)row * 32 + c2]);
        s0 += f.x; q0 += f.x * f.x;
        s1 += f.y; q1 += f.y * f.y;
    }
    __shared__ float sh[4][256];
    sh[0][tid] = s0; sh[1][tid] = q0; sh[2][tid] = s1; sh[3][tid] = q1;
    __syncthreads();
    if (tid < 32) {
        float ts0 = 0.f, tq0 = 0.f, ts1 = 0.f, tq1 = 0.f;
#pragma unroll
        for (int j = 0; j < 8; ++j) {
            int idx = tid + 32 * j;
            ts0 += sh[0][idx]; tq0 += sh[1][idx];
            ts1 += sh[2][idx]; tq1 += sh[3][idx];
        }
        partials[blockIdx.x * 128 + 2 * tid]          = ts0;
        partials[blockIdx.x * 128 + 2 * tid + 1]      = ts1;
        partials[blockIdx.x * 128 + 64 + 2 * tid]     = tq0;
        partials[blockIdx.x * 128 + 64 + 2 * tid + 1] = tq1;
    }
}

__global__ __launch_bounds__(256) void stats_float_kernel(
    const float* __restrict__ y, float* __restrict__ partials)
{
    const int tid = threadIdx.x;
    const int c = tid & 63, r = tid >> 6;
    float s = 0.f, q = 0.f;
    for (int row = blockIdx.x * 4 + r; row < NV; row += 2048) {
        float v = y[(size_t)row * 64 + c];
        s += v; q += v * v;
    }
    __shared__ float sh[512];
    sh[tid] = s; sh[256 + tid] = q;
    __syncthreads();
    if (tid < 64) {
        float ts = sh[tid] + sh[tid + 64] + sh[tid + 128] + sh[tid + 192];
        float tq = sh[256 + tid] + sh[256 + tid + 64] + sh[256 + tid + 128] + sh[256 + tid + 192];
        partials[blockIdx.x * 128 + tid]      = ts;
        partials[blockIdx.x * 128 + 64 + tid] = tq;
    }
}

__global__ void finalize_stats_kernel(
    const float* __restrict__ partials, const float* __restrict__ gamma,
    const float* __restrict__ beta, float* __restrict__ ss)
{
    const int c = threadIdx.x;   // 0..63
    float s = 0.f, q = 0.f;
    for (int b = 0; b < 512; ++b) {
        s += partials[b * 128 + c];
        q += partials[b * 128 + 64 + c];
    }
    const float invN = 1.0f / (float)NV;
    float mean  = s * invN;
    float var   = q * invN - mean * mean;
    float scale = gamma[c] * rsqrtf(var + 1e-5f);
    ss[c]      = scale;
    ss[64 + c] = beta[c] - mean * scale;
}

// ============================================================================
// Fused BN + ReLU (half, in place) and BN + residual + ReLU (float)
// ============================================================================
__global__ __launch_bounds__(256) void bn_act_half_kernel(
    __half2* __restrict__ y, const float* __restrict__ ss)
{
    long i = (long)blockIdx.x * 256 + threadIdx.x;   // over NV*32 half2s
    const int cb = (int)(i & 31);
    float2 f = __half22float2(y[i]);
    float rx = fmaf(f.x, ss[2 * cb],     ss[64 + 2 * cb]);
    float ry = fmaf(f.y, ss[2 * cb + 1], ss[64 + 2 * cb + 1]);
    y[i] = __floats2half2_rn(fmaxf(rx, 0.f), fmaxf(ry, 0.f));
}

__global__ __launch_bounds__(256) void bn_act_float_kernel(
    float* __restrict__ y, const float* __restrict__ ss,
    const float* __restrict__ residual)
{
    long i = (long)blockIdx.x * 256 + threadIdx.x;   // over NV*16 float4s
    float4 v = reinterpret_cast<float4*>(y)[i];
    const int cb = (int)(i & 15);
    float4 sc = reinterpret_cast<const float4*>(ss)[cb];
    float4 sh = reinterpret_cast<const float4*>(ss + 64)[cb];
    float4 f = reinterpret_cast<const float4*>(residual)[i];
    float4 r;
    r.x = fmaxf(fmaf(v.x, sc.x, sh.x) + f.x, 0.f);
    r.y = fmaxf(fmaf(v.y, sc.y, sh.y) + f.y, 0.f);
    r.z = fmaxf(fmaf(v.z, sc.z, sh.z) + f.z, 0.f);
    r.w = fmaxf(fmaf(v.w, sc.w, sh.w) + f.w, 0.f);
    reinterpret_cast<float4*>(y)[i] = r;
}

// ============================================================================
// kernel_launch
// ============================================================================
extern "C" void kernel_launch(void* const* d_in, const int* in_sizes, int n_in,
                              void* d_out, int out_size)
{
    const float* features = (const float*)d_in[0];
    const int*   nbr      = (const int*)  d_in[1];
    const float* valid    = (const float*)d_in[2];
    const float* W1       = (const float*)d_in[3];
    const float* gamma1   = (const float*)d_in[4];
    const float* beta1    = (const float*)d_in[5];
    const float* W2       = (const float*)d_in[6];
    const float* gamma2   = (const float*)d_in[7];
    const float* beta2    = (const float*)d_in[8];
    float* out = (float*)d_out;

    __half *xh, *y1h, *Wt;
    float *partials, *ss1, *ss2;
    cudaGetSymbolAddress((void**)&xh,       g_xh);
    cudaGetSymbolAddress((void**)&y1h,      g_y1h);
    cudaGetSymbolAddress((void**)&Wt,       g_Wt);
    cudaGetSymbolAddress((void**)&partials, g_partials);
    cudaGetSymbolAddress((void**)&ss1,      g_ss1);
    cudaGetSymbolAddress((void**)&ss2,      g_ss2);

    cudaFuncSetAttribute(conv_kernel<__half>, cudaFuncAttributeMaxDynamicSharedMemorySize, SMEM_BYTES);
    cudaFuncSetAttribute(conv_kernel<float>,  cudaFuncAttributeMaxDynamicSharedMemorySize, SMEM_BYTES);

    const int convBlocks = (NV + MT - 1) / MT;     // 3907
    const int cvtBlocks  = (int)(((long)NV * 16) / 256);       // 31250, exact
    const int bnHBlocks  = (int)(((long)NV * 32) / 256);       // 62500, exact
    const int wBlocks    = (2 * KK * 4096 + 255) / 256;

    cvt_features_kernel<<<cvtBlocks, 256>>>((const float4*)features, (__half2*)xh);
    cvt_weights_kernel<<<wBlocks, 256>>>(W1, W2, Wt);

    conv_kernel<__half><<<convBlocks, 256, SMEM_BYTES>>>(xh, nbr, valid, Wt, y1h);
    stats_half_kernel<<<512, 256>>>((const __half2*)y1h, partials);
    finalize_stats_kernel<<<1, 64>>>(partials, gamma1, beta1, ss1);
    bn_act_half_kernel<<<bnHBlocks, 256>>>((__half2*)y1h, ss1);

    conv_kernel<float><<<convBlocks, 256, SMEM_BYTES>>>(y1h, nbr, valid, Wt + (size_t)KK * 4096, out);
    stats_float_kernel<<<512, 256>>>(out, partials);
    finalize_stats_kernel<<<1, 64>>>(partials, gamma2, beta2, ss2);
    bn_act_float_kernel<<<cvtBlocks, 256>>>(out, ss2, features);
}

// round 10
// speedup vs baseline: 1.7440x; 1.2119x over previous
#include <cuda_runtime.h>
#include <cuda_fp16.h>
#include <cstdint>

#define NV      500000
#define KK      27
#define MT      128                        // rows per conv block tile
#define AST     72                         // A smem row stride (halves) — conflict-free frag reads
#define BST     72                         // B smem row stride (halves)
#define A_TILE  (128 * AST)                // 9216 halves (one offset's 128x64 tile)
#define A_BUF2  (2 * A_TILE)               // per stage: 2 offset tiles
#define B_TILE  (64 * BST)                 // 4608 halves (one 64x64 W mat)
#define B_BUF2  (2 * B_TILE)
#define SMEM_TOTAL ((2 * A_BUF2 + 2 * B_BUF2) * 2)   // 110592 B
#define NSTAGE  ((KK + 1) / 2)             // 14 (last stage single offset)

// ---- scratch (static device globals: allocation-free per harness rules) ----
__device__ __half g_xh[(size_t)NV * 64];      // features fp16
__device__ __half g_y1h[(size_t)NV * 64];     // conv1 out / conv2 in
__device__ __half g_Wt[2][KK * 64 * 64];      // fp16 weights [k][cout][cin]
__device__ int    g_pnbr[(size_t)KK * NV];    // packed: idx if valid else -1
__device__ float  g_partials[512 * 128];
__device__ float  g_ss1[128];
__device__ float  g_ss2[128];

// ============================================================================
// Gather-GEMM submanifold conv, fp16 m16n8k16 mma.sync, fp32 accum.
// Block: 256 threads (8 warps), tile 128 rows x 64 cols.
// TWO k-offsets per barrier stage (14 stages), double-buffered A & W smem.
// Invalid neighbor rows are zero-filled with NO global load.
// ============================================================================
template <typename OutT>
__global__ __launch_bounds__(256, 2) void conv_kernel(
    const __half* __restrict__ x, const int* __restrict__ pnbr,
    const __half* __restrict__ Wt, OutT* __restrict__ y)
{
    extern __shared__ __align__(16) __half smem[];
    __half* As = smem;                       // 2 buf x 2 offset-tiles
    __half* Bs = smem + 2 * A_BUF2;          // 2 buf x 2 W mats

    const int tid  = threadIdx.x;
    const int warp = tid >> 5, lane = tid & 31;
    const int g    = lane >> 2, tig = lane & 3;     // groupID / thread-in-group
    const int rowBase = blockIdx.x * MT;
    const int arow = tid & 127;                     // gather row within tile
    const int aoff = tid >> 7;                      // which offset of the pair
    const int grow = rowBase + arow;
    const int m0   = warp * 16;

    float acc[8][4];
#pragma unroll
    for (int n = 0; n < 8; ++n)
#pragma unroll
        for (int j = 0; j < 4; ++j) acc[n][j] = 0.f;

    uint4 areg[8], wreg[4];
    auto prefetch = [&](int s) {
        const int ko = 2 * s + aoff;
        int pk = (ko < KK && grow < NV) ? pnbr[(size_t)ko * NV + grow] : -1;
#pragma unroll
        for (int i = 0; i < 8; ++i) areg[i] = make_uint4(0, 0, 0, 0);
        if (pk >= 0) {
            const uint4* src = reinterpret_cast<const uint4*>(x + (size_t)pk * 64);
#pragma unroll
            for (int i = 0; i < 8; ++i) areg[i] = src[i];
        }
        const int mats = (KK - 2 * s) < 2 ? (KK - 2 * s) : 2;
        const int qlim = mats * 512;                 // uint4s in this stage's W
        const uint4* ws = reinterpret_cast<const uint4*>(Wt + (size_t)(2 * s) * 4096);
#pragma unroll
        for (int i = 0; i < 4; ++i) {
            int q = tid + 256 * i;
            wreg[i] = (q < qlim) ? ws[q] : make_uint4(0, 0, 0, 0);
        }
    };
    prefetch(0);

    for (int s = 0; s < NSTAGE; ++s) {
        const int buf = s & 1;
        // ---- store staged tiles ----
        {
            __half* adst = As + buf * A_BUF2 + aoff * A_TILE + arow * AST;
#pragma unroll
            for (int i = 0; i < 8; ++i)
                *reinterpret_cast<uint4*>(adst + i * 8) = areg[i];
            __half* bb = Bs + buf * B_BUF2;
#pragma unroll
            for (int i = 0; i < 4; ++i) {
                int q = tid + 256 * i;               // 1024 x 16B, 8 per 64-row
                *reinterpret_cast<uint4*>(bb + (q >> 3) * BST + (q & 7) * 8) = wreg[i];
            }
        }
        __syncthreads();

        if (s + 1 < NSTAGE) prefetch(s + 1);         // overlaps with MMA below

        const int npair = (KK - 2 * s) < 2 ? (KK - 2 * s) : 2;
        for (int h = 0; h < npair; ++h) {
            const __half* A = As + buf * A_BUF2 + h * A_TILE;
            const __half* B = Bs + buf * B_BUF2 + h * B_TILE;
#pragma unroll
            for (int kc = 0; kc < 4; ++kc) {
                unsigned a0 = *reinterpret_cast<const unsigned*>(A + (m0 + g)     * AST + kc * 16 + 2 * tig);
                unsigned a1 = *reinterpret_cast<const unsigned*>(A + (m0 + g + 8) * AST + kc * 16 + 2 * tig);
                unsigned a2 = *reinterpret_cast<const unsigned*>(A + (m0 + g)     * AST + kc * 16 + 2 * tig + 8);
                unsigned a3 = *reinterpret_cast<const unsigned*>(A + (m0 + g + 8) * AST + kc * 16 + 2 * tig + 8);
#pragma unroll
                for (int n = 0; n < 8; ++n) {
                    unsigned b0 = *reinterpret_cast<const unsigned*>(B + (n * 8 + g) * BST + kc * 16 + 2 * tig);
                    unsigned b1 = *reinterpret_cast<const unsigned*>(B + (n * 8 + g) * BST + kc * 16 + 2 * tig + 8);
                    asm volatile(
                        "mma.sync.aligned.m16n8k16.row.col.f32.f16.f16.f32 "
                        "{%0,%1,%2,%3},{%4,%5,%6,%7},{%8,%9},{%0,%1,%2,%3};\n"
                        : "+f"(acc[n][0]), "+f"(acc[n][1]), "+f"(acc[n][2]), "+f"(acc[n][3])
                        : "r"(a0), "r"(a1), "r"(a2), "r"(a3), "r"(b0), "r"(b1));
                }
            }
        }
        // no trailing sync: next iteration's __syncthreads (other buffer)
        // separates this MMA's LDS from the s+2 overwrite of this buffer.
    }

    // ---- epilogue: c{0,1}->row g, c{2,3}->row g+8 ----
    const int r0 = rowBase + m0 + g;
    const int r1 = r0 + 8;
#pragma unroll
    for (int n = 0; n < 8; ++n) {
        int col = n * 8 + 2 * tig;
        if constexpr (sizeof(OutT) == 4) {
            if (r0 < NV)
                *reinterpret_cast<float2*>((float*)y + (size_t)r0 * 64 + col) = make_float2(acc[n][0], acc[n][1]);
            if (r1 < NV)
                *reinterpret_cast<float2*>((float*)y + (size_t)r1 * 64 + col) = make_float2(acc[n][2], acc[n][3]);
        } else {
            if (r0 < NV)
                *reinterpret_cast<__half2*>((__half*)y + (size_t)r0 * 64 + col) = __floats2half2_rn(acc[n][0], acc[n][1]);
            if (r1 < NV)
                *reinterpret_cast<__half2*>((__half*)y + (size_t)r1 * 64 + col) = __floats2half2_rn(acc[n][2], acc[n][3]);
        }
    }
}

// ============================================================================
// One-shot converters / packers
// ============================================================================
__global__ __launch_bounds__(256) void cvt_features_kernel(
    const float4* __restrict__ x, __half2* __restrict__ xh)
{
    long i = (long)blockIdx.x * 256 + threadIdx.x;   // NV*16 float4s, exact
    float4 v = x[i];
    xh[2 * i]     = __floats2half2_rn(v.x, v.y);
    xh[2 * i + 1] = __floats2half2_rn(v.z, v.w);
}

__global__ void cvt_weights_kernel(
    const float* __restrict__ W1, const float* __restrict__ W2,
    __half* __restrict__ Wt)   // [2][27][cout][cin]
{
    int o = blockIdx.x * 256 + threadIdx.x;
    if (o >= 2 * KK * 4096) return;
    int wsel = o / (KK * 4096);
    int rem  = o % (KK * 4096);
    int k = rem >> 12, t = rem & 4095;
    int co = t >> 6, ci = t & 63;
    const float* W = wsel ? W2 : W1;
    Wt[o] = __float2half_rn(W[(size_t)k * 4096 + ci * 64 + co]);
}

__global__ void pack_nbr_kernel(const int* __restrict__ nbr,
                                const float* __restrict__ valid,
                                int* __restrict__ pnbr)
{
    long i = (long)blockIdx.x * 256 + threadIdx.x;
    if (i >= (long)KK * NV) return;
    pnbr[i] = (valid[i] > 0.5f) ? nbr[i] : -1;
}

// ============================================================================
// BN statistics: deterministic two-stage reduction (no float atomics)
// ============================================================================
__global__ __launch_bounds__(256) void stats_half_kernel(
    const __half2* __restrict__ y, float* __restrict__ partials)
{
    const int tid = threadIdx.x;
    const int c2 = tid & 31, r = tid >> 5;
    float s0 = 0.f, q0 = 0.f, s1 = 0.f, q1 = 0.f;
    for (int row = blockIdx.x * 8 + r; row < NV; row += 4096) {
        float2 f = __half22float2(y[(size_t)row * 32 + c2]);
        s0 += f.x; q0 += f.x * f.x;
        s1 += f.y; q1 += f.y * f.y;
    }
    __shared__ float sh[4][256];
    sh[0][tid] = s0; sh[1][tid] = q0; sh[2][tid] = s1; sh[3][tid] = q1;
    __syncthreads();
    if (tid < 32) {
        float ts0 = 0.f, tq0 = 0.f, ts1 = 0.f, tq1 = 0.f;
#pragma unroll
        for (int j = 0; j < 8; ++j) {
            int idx = tid + 32 * j;
            ts0 += sh[0][idx]; tq0 += sh[1][idx];
            ts1 += sh[2][idx]; tq1 += sh[3][idx];
        }
        partials[blockIdx.x * 128 + 2 * tid]          = ts0;
        partials[blockIdx.x * 128 + 2 * tid + 1]      = ts1;
        partials[blockIdx.x * 128 + 64 + 2 * tid]     = tq0;
        partials[blockIdx.x * 128 + 64 + 2 * tid + 1] = tq1;
    }
}

__global__ __launch_bounds__(256) void stats_float_kernel(
    const float* __restrict__ y, float* __restrict__ partials)
{
    const int tid = threadIdx.x;
    const int c = tid & 63, r = tid >> 6;
    float s = 0.f, q = 0.f;
    for (int row = blockIdx.x * 4 + r; row < NV; row += 2048) {
        float v = y[(size_t)row * 64 + c];
        s += v; q += v * v;
    }
    __shared__ float sh[512];
    sh[tid] = s; sh[256 + tid] = q;
    __syncthreads();
    if (tid < 64) {
        float ts = sh[tid] + sh[tid + 64] + sh[tid + 128] + sh[tid + 192];
        float tq = sh[256 + tid] + sh[256 + tid + 64] + sh[256 + tid + 128] + sh[256 + tid + 192];
        partials[blockIdx.x * 128 + tid]      = ts;
        partials[blockIdx.x * 128 + 64 + tid] = tq;
    }
}

__global__ void finalize_stats_kernel(
    const float* __restrict__ partials, const float* __restrict__ gamma,
    const float* __restrict__ beta, float* __restrict__ ss)
{
    const int c = threadIdx.x;   // 0..63
    float s = 0.f, q = 0.f;
    for (int b = 0; b < 512; ++b) {
        s += partials[b * 128 + c];
        q += partials[b * 128 + 64 + c];
    }
    const float invN = 1.0f / (float)NV;
    float mean  = s * invN;
    float var   = q * invN - mean * mean;
    float scale = gamma[c] * rsqrtf(var + 1e-5f);
    ss[c]      = scale;
    ss[64 + c] = beta[c] - mean * scale;
}

// ============================================================================
// Fused BN + ReLU (half, in place) and BN + residual + ReLU (float)
// ============================================================================
__global__ __launch_bounds__(256) void bn_act_half_kernel(
    __half2* __restrict__ y, const float* __restrict__ ss)
{
    long i = (long)blockIdx.x * 256 + threadIdx.x;   // NV*32 half2s, exact
    const int cb = (int)(i & 31);
    float2 f = __half22float2(y[i]);
    float rx = fmaf(f.x, ss[2 * cb],     ss[64 + 2 * cb]);
    float ry = fmaf(f.y, ss[2 * cb + 1], ss[64 + 2 * cb + 1]);
    y[i] = __floats2half2_rn(fmaxf(rx, 0.f), fmaxf(ry, 0.f));
}

__global__ __launch_bounds__(256) void bn_act_float_kernel(
    float* __restrict__ y, const float* __restrict__ ss,
    const float* __restrict__ residual)
{
    long i = (long)blockIdx.x * 256 + threadIdx.x;   // NV*16 float4s, exact
    float4 v = reinterpret_cast<float4*>(y)[i];
    const int cb = (int)(i & 15);
    float4 sc = reinterpret_cast<const float4*>(ss)[cb];
    float4 sh = reinterpret_cast<const float4*>(ss + 64)[cb];
    float4 f = reinterpret_cast<const float4*>(residual)[i];
    float4 r;
    r.x = fmaxf(fmaf(v.x, sc.x, sh.x) + f.x, 0.f);
    r.y = fmaxf(fmaf(v.y, sc.y, sh.y) + f.y, 0.f);
    r.z = fmaxf(fmaf(v.z, sc.z, sh.z) + f.z, 0.f);
    r.w = fmaxf(fmaf(v.w, sc.w, sh.w) + f.w, 0.f);
    reinterpret_cast<float4*>(y)[i] = r;
}

// ============================================================================
// kernel_launch
// ============================================================================
extern "C" void kernel_launch(void* const* d_in, const int* in_sizes, int n_in,
                              void* d_out, int out_size)
{
    const float* features = (const float*)d_in[0];
    const int*   nbr      = (const int*)  d_in[1];
    const float* valid    = (const float*)d_in[2];
    const float* W1       = (const float*)d_in[3];
    const float* gamma1   = (const float*)d_in[4];
    const float* beta1    = (const float*)d_in[5];
    const float* W2       = (const float*)d_in[6];
    const float* gamma2   = (const float*)d_in[7];
    const float* beta2    = (const float*)d_in[8];
    float* out = (float*)d_out;

    __half *xh, *y1h, *Wt;
    int* pnbr;
    float *partials, *ss1, *ss2;
    cudaGetSymbolAddress((void**)&xh,       g_xh);
    cudaGetSymbolAddress((void**)&y1h,      g_y1h);
    cudaGetSymbolAddress((void**)&Wt,       g_Wt);
    cudaGetSymbolAddress((void**)&pnbr,     g_pnbr);
    cudaGetSymbolAddress((void**)&partials, g_partials);
    cudaGetSymbolAddress((void**)&ss1,      g_ss1);
    cudaGetSymbolAddress((void**)&ss2,      g_ss2);

    cudaFuncSetAttribute(conv_kernel<__half>, cudaFuncAttributeMaxDynamicSharedMemorySize, SMEM_TOTAL);
    cudaFuncSetAttribute(conv_kernel<float>,  cudaFuncAttributeMaxDynamicSharedMemorySize, SMEM_TOTAL);

    const int convBlocks = (NV + MT - 1) / MT;                 // 3907
    const int cvtBlocks  = (int)(((long)NV * 16) / 256);       // 31250, exact
    const int bnHBlocks  = (int)(((long)NV * 32) / 256);       // 62500, exact
    const int wBlocks    = (2 * KK * 4096 + 255) / 256;
    const int pkBlocks   = (int)(((long)KK * NV + 255) / 256);

    cvt_features_kernel<<<cvtBlocks, 256>>>((const float4*)features, (__half2*)xh);
    cvt_weights_kernel<<<wBlocks, 256>>>(W1, W2, Wt);
    pack_nbr_kernel<<<pkBlocks, 256>>>(nbr, valid, pnbr);

    conv_kernel<__half><<<convBlocks, 256, SMEM_TOTAL>>>(xh, pnbr, Wt, y1h);
    stats_half_kernel<<<512, 256>>>((const __half2*)y1h, partials);
    finalize_stats_kernel<<<1, 64>>>(partials, gamma1, beta1, ss1);
    bn_act_half_kernel<<<bnHBlocks, 256>>>((__half2*)y1h, ss1);

    conv_kernel<float><<<convBlocks, 256, SMEM_TOTAL>>>(y1h, pnbr, Wt + (size_t)KK * 4096, out);
    stats_float_kernel<<<512, 256>>>(out, partials);
    finalize_stats_kernel<<<1, 64>>>(partials, gamma2, beta2, ss2);
    bn_act_float_kernel<<<cvtBlocks, 256>>>(out, ss2, features);
}

// round 11
// speedup vs baseline: 2.0435x; 1.1718x over previous
#include <cuda_runtime.h>
#include <cuda_fp16.h>
#include <cstdint>

#define NV      500000
#define KK      27
#define MROWS   256                        // rows per conv block (8 warps x M=32)
#define AST     72                         // A smem row stride (halves) = 144 B
#define BST     72                         // B smem row stride (halves)
#define A_BUF_H (MROWS * AST)              // 18432 halves = 36864 B per buffer
#define B_BUF_H (64 * BST)                 // 4608 halves  = 9216 B per buffer
#define SMEM_TOTAL ((2 * A_BUF_H + 2 * B_BUF_H) * 2)   // 92160 B

// ---- scratch (static device globals: allocation-free per harness rules) ----
__device__ __half g_xh[(size_t)NV * 64];      // features fp16
__device__ __half g_y1h[(size_t)NV * 64];     // conv1 out / conv2 in
__device__ __half g_Wt[2][KK * 64 * 64];      // fp16 weights [k][cout][cin]
__device__ int    g_pnbr[(size_t)KK * NV];    // packed: idx if valid else -1
__device__ float  g_partials[512 * 128];
__device__ float  g_ss1[128];
__device__ float  g_ss2[128];

__device__ __forceinline__ uint32_t smem_u32(const void* p) {
    uint32_t a;
    asm("{ .reg .u64 t; cvta.to.shared.u64 t, %1; cvt.u32.u64 %0, t; }" : "=r"(a) : "l"(p));
    return a;
}
__device__ __forceinline__ void cpa16(uint32_t dst, const void* src, int sz) {
    asm volatile("cp.async.ca.shared.global [%0], [%1], 16, %2;"
                 :: "r"(dst), "l"(src), "r"(sz) : "memory");
}

// ============================================================================
// Gather-GEMM submanifold conv, fp16 m16n8k16 mma.sync, fp32 accum.
// Block: 256 threads (8 warps), tile 256 rows x 64 cols; each warp M=32.
// One k-offset per stage, double-buffered via cp.async (zero-fill for
// invalid neighbors -> no LDG, no register staging).
// ============================================================================
template <typename OutT>
__global__ __launch_bounds__(256, 2) void conv_kernel(
    const __half* __restrict__ x, const int* __restrict__ pnbr,
    const __half* __restrict__ Wt, OutT* __restrict__ y)
{
    extern __shared__ __align__(16) __half smem[];
    const uint32_t sb = smem_u32(smem);

    const int tid  = threadIdx.x;
    const int warp = tid >> 5, lane = tid & 31;
    const int g    = lane >> 2, tig = lane & 3;     // groupID / thread-in-group
    const int rowBase = blockIdx.x * MROWS;
    const int grow = rowBase + tid;                 // one gather row per thread

    // byte bases of the double-buffered tiles
    const uint32_t Ab[2] = { sb, sb + (uint32_t)A_BUF_H * 2 };
    const uint32_t Bb[2] = { sb + 4 * (uint32_t)A_BUF_H,
                             sb + 4 * (uint32_t)A_BUF_H + (uint32_t)B_BUF_H * 2 };

    float acc[16][4];
#pragma unroll
    for (int n = 0; n < 16; ++n)
#pragma unroll
        for (int j = 0; j < 4; ++j) acc[n][j] = 0.f;

    auto issue = [&](int k, int buf) {
        int pk = (grow < NV) ? pnbr[(size_t)k * NV + grow] : -1;
        const __half* srow = x + (size_t)(pk >= 0 ? pk : 0) * 64;
        int sz = (pk >= 0) ? 16 : 0;                 // zero-fill invalid rows
        uint32_t adst = Ab[buf] + (uint32_t)tid * 144;
#pragma unroll
        for (int i = 0; i < 8; ++i)
            cpa16(adst + i * 16, srow + i * 8, sz);
        const __half* wsrc = Wt + (size_t)k * 4096;
#pragma unroll
        for (int i = 0; i < 2; ++i) {
            int q = tid + 256 * i;                   // 512 x 16B, 8 per 64-row
            cpa16(Bb[buf] + (q >> 3) * 144 + (q & 7) * 16, wsrc + q * 8, 16);
        }
        asm volatile("cp.async.commit_group;" ::: "memory");
    };

    issue(0, 0);

    for (int k = 0; k < KK; ++k) {
        const int buf = k & 1;
        if (k + 1 < KK) {
            issue(k + 1, buf ^ 1);
            asm volatile("cp.async.wait_group 1;" ::: "memory");
        } else {
            asm volatile("cp.async.wait_group 0;" ::: "memory");
        }
        __syncthreads();                             // stage k visible to all

        const __half* A = smem + (size_t)buf * A_BUF_H;
        const __half* B = smem + 2 * (size_t)A_BUF_H + (size_t)buf * B_BUF_H;
#pragma unroll
        for (int kc = 0; kc < 4; ++kc) {
            unsigned a[2][4];
#pragma unroll
            for (int mt = 0; mt < 2; ++mt) {
                const int r = warp * 32 + mt * 16 + g;
                a[mt][0] = *reinterpret_cast<const unsigned*>(A + r       * AST + kc * 16 + 2 * tig);
                a[mt][1] = *reinterpret_cast<const unsigned*>(A + (r + 8) * AST + kc * 16 + 2 * tig);
                a[mt][2] = *reinterpret_cast<const unsigned*>(A + r       * AST + kc * 16 + 2 * tig + 8);
                a[mt][3] = *reinterpret_cast<const unsigned*>(A + (r + 8) * AST + kc * 16 + 2 * tig + 8);
            }
#pragma unroll
            for (int n = 0; n < 8; ++n) {
                unsigned b0 = *reinterpret_cast<const unsigned*>(B + (n * 8 + g) * BST + kc * 16 + 2 * tig);
                unsigned b1 = *reinterpret_cast<const unsigned*>(B + (n * 8 + g) * BST + kc * 16 + 2 * tig + 8);
                asm volatile(
                    "mma.sync.aligned.m16n8k16.row.col.f32.f16.f16.f32 "
                    "{%0,%1,%2,%3},{%4,%5,%6,%7},{%8,%9},{%0,%1,%2,%3};\n"
                    : "+f"(acc[n][0]), "+f"(acc[n][1]), "+f"(acc[n][2]), "+f"(acc[n][3])
                    : "r"(a[0][0]), "r"(a[0][1]), "r"(a[0][2]), "r"(a[0][3]), "r"(b0), "r"(b1));
                asm volatile(
                    "mma.sync.aligned.m16n8k16.row.col.f32.f16.f16.f32 "
                    "{%0,%1,%2,%3},{%4,%5,%6,%7},{%8,%9},{%0,%1,%2,%3};\n"
                    : "+f"(acc[8 + n][0]), "+f"(acc[8 + n][1]), "+f"(acc[8 + n][2]), "+f"(acc[8 + n][3])
                    : "r"(a[1][0]), "r"(a[1][1]), "r"(a[1][2]), "r"(a[1][3]), "r"(b0), "r"(b1));
            }
        }
        __syncthreads();                             // all reads done before buf reuse
    }

    // ---- epilogue: c{0,1}->row g, c{2,3}->row g+8 ----
#pragma unroll
    for (int mt = 0; mt < 2; ++mt) {
        const int r0 = rowBase + warp * 32 + mt * 16 + g;
        const int r1 = r0 + 8;
#pragma unroll
        for (int n = 0; n < 8; ++n) {
            const float* a = acc[mt * 8 + n];
            int col = n * 8 + 2 * tig;
            if constexpr (sizeof(OutT) == 4) {
                if (r0 < NV)
                    *reinterpret_cast<float2*>((float*)y + (size_t)r0 * 64 + col) = make_float2(a[0], a[1]);
                if (r1 < NV)
                    *reinterpret_cast<float2*>((float*)y + (size_t)r1 * 64 + col) = make_float2(a[2], a[3]);
            } else {
                if (r0 < NV)
                    *reinterpret_cast<__half2*>((__half*)y + (size_t)r0 * 64 + col) = __floats2half2_rn(a[0], a[1]);
                if (r1 < NV)
                    *reinterpret_cast<__half2*>((__half*)y + (size_t)r1 * 64 + col) = __floats2half2_rn(a[2], a[3]);
            }
        }
    }
}

// ============================================================================
// One-shot converters / packers
// ============================================================================
__global__ __launch_bounds__(256) void cvt_features_kernel(
    const float4* __restrict__ x, __half2* __restrict__ xh)
{
    long i = (long)blockIdx.x * 256 + threadIdx.x;   // NV*16 float4s, exact
    float4 v = x[i];
    xh[2 * i]     = __floats2half2_rn(v.x, v.y);
    xh[2 * i + 1] = __floats2half2_rn(v.z, v.w);
}

__global__ void cvt_weights_kernel(
    const float* __restrict__ W1, const float* __restrict__ W2,
    __half* __restrict__ Wt)   // [2][27][cout][cin]
{
    int o = blockIdx.x * 256 + threadIdx.x;
    if (o >= 2 * KK * 4096) return;
    int wsel = o / (KK * 4096);
    int rem  = o % (KK * 4096);
    int k = rem >> 12, t = rem & 4095;
    int co = t >> 6, ci = t & 63;
    const float* W = wsel ? W2 : W1;
    Wt[o] = __float2half_rn(W[(size_t)k * 4096 + ci * 64 + co]);
}

__global__ void pack_nbr_kernel(const int* __restrict__ nbr,
                                const float* __restrict__ valid,
                                int* __restrict__ pnbr)
{
    long i = (long)blockIdx.x * 256 + threadIdx.x;
    if (i >= (long)KK * NV) return;
    pnbr[i] = (valid[i] > 0.5f) ? nbr[i] : -1;
}

// ============================================================================
// BN statistics: deterministic two-stage reduction (no float atomics)
// ============================================================================
__global__ __launch_bounds__(256) void stats_half_kernel(
    const __half2* __restrict__ y, float* __restrict__ partials)
{
    const int tid = threadIdx.x;
    const int c2 = tid & 31, r = tid >> 5;
    float s0 = 0.f, q0 = 0.f, s1 = 0.f, q1 = 0.f;
    for (int row = blockIdx.x * 8 + r; row < NV; row += 4096) {
        float2 f = __half22float2(y[(size_t)row * 32 + c2]);
        s0 += f.x; q0 += f.x * f.x;
        s1 += f.y; q1 += f.y * f.y;
    }
    __shared__ float sh[4][256];
    sh[0][tid] = s0; sh[1][tid] = q0; sh[2][tid] = s1; sh[3][tid] = q1;
    __syncthreads();
    if (tid < 32) {
        float ts0 = 0.f, tq0 = 0.f, ts1 = 0.f, tq1 = 0.f;
#pragma unroll
        for (int j = 0; j < 8; ++j) {
            int idx = tid + 32 * j;
            ts0 += sh[0][idx]; tq0 += sh[1][idx];
            ts1 += sh[2][idx]; tq1 += sh[3][idx];
        }
        partials[blockIdx.x * 128 + 2 * tid]          = ts0;
        partials[blockIdx.x * 128 + 2 * tid + 1]      = ts1;
        partials[blockIdx.x * 128 + 64 + 2 * tid]     = tq0;
        partials[blockIdx.x * 128 + 64 + 2 * tid + 1] = tq1;
    }
}

__global__ __launch_bounds__(256) void stats_float_kernel(
    const float* __restrict__ y, float* __restrict__ partials)
{
    const int tid = threadIdx.x;
    const int c = tid & 63, r = tid >> 6;
    float s = 0.f, q = 0.f;
    for (int row = blockIdx.x * 4 + r; row < NV; row += 2048) {
        float v = y[(size_t)row * 64 + c];
        s += v; q += v * v;
    }
    __shared__ float sh[512];
    sh[tid] = s; sh[256 + tid] = q;
    __syncthreads();
    if (tid < 64) {
        float ts = sh[tid] + sh[tid + 64] + sh[tid + 128] + sh[tid + 192];
        float tq = sh[256 + tid] + sh[256 + tid + 64] + sh[256 + tid + 128] + sh[256 + tid + 192];
        partials[blockIdx.x * 128 + tid]      = ts;
        partials[blockIdx.x * 128 + 64 + tid] = tq;
    }
}

__global__ void finalize_stats_kernel(
    const float* __restrict__ partials, const float* __restrict__ gamma,
    const float* __restrict__ beta, float* __restrict__ ss)
{
    const int c = threadIdx.x;   // 0..63
    float s = 0.f, q = 0.f;
    for (int b = 0; b < 512; ++b) {
        s += partials[b * 128 + c];
        q += partials[b * 128 + 64 + c];
    }
    const float invN = 1.0f / (float)NV;
    float mean  = s * invN;
    float var   = q * invN - mean * mean;
    float scale = gamma[c] * rsqrtf(var + 1e-5f);
    ss[c]      = scale;
    ss[64 + c] = beta[c] - mean * scale;
}

// ============================================================================
// Fused BN + ReLU (half, in place) and BN + residual + ReLU (float)
// ============================================================================
__global__ __launch_bounds__(256) void bn_act_half_kernel(
    __half2* __restrict__ y, const float* __restrict__ ss)
{
    long i = (long)blockIdx.x * 256 + threadIdx.x;   // NV*32 half2s, exact
    const int cb = (int)(i & 31);
    float2 f = __half22float2(y[i]);
    float rx = fmaf(f.x, ss[2 * cb],     ss[64 + 2 * cb]);
    float ry = fmaf(f.y, ss[2 * cb + 1], ss[64 + 2 * cb + 1]);
    y[i] = __floats2half2_rn(fmaxf(rx, 0.f), fmaxf(ry, 0.f));
}

__global__ __launch_bounds__(256) void bn_act_float_kernel(
    float* __restrict__ y, const float* __restrict__ ss,
    const float* __restrict__ residual)
{
    long i = (long)blockIdx.x * 256 + threadIdx.x;   // NV*16 float4s, exact
    float4 v = reinterpret_cast<float4*>(y)[i];
    const int cb = (int)(i & 15);
    float4 sc = reinterpret_cast<const float4*>(ss)[cb];
    float4 sh = reinterpret_cast<const float4*>(ss + 64)[cb];
    float4 f = reinterpret_cast<const float4*>(residual)[i];
    float4 r;
    r.x = fmaxf(fmaf(v.x, sc.x, sh.x) + f.x, 0.f);
    r.y = fmaxf(fmaf(v.y, sc.y, sh.y) + f.y, 0.f);
    r.z = fmaxf(fmaf(v.z, sc.z, sh.z) + f.z, 0.f);
    r.w = fmaxf(fmaf(v.w, sc.w, sh.w) + f.w, 0.f);
    reinterpret_cast<float4*>(y)[i] = r;
}

// ============================================================================
// kernel_launch
// ============================================================================
extern "C" void kernel_launch(void* const* d_in, const int* in_sizes, int n_in,
                              void* d_out, int out_size)
{
    const float* features = (const float*)d_in[0];
    const int*   nbr      = (const int*)  d_in[1];
    const float* valid    = (const float*)d_in[2];
    const float* W1       = (const float*)d_in[3];
    const float* gamma1   = (const float*)d_in[4];
    const float* beta1    = (const float*)d_in[5];
    const float* W2       = (const float*)d_in[6];
    const float* gamma2   = (const float*)d_in[7];
    const float* beta2    = (const float*)d_in[8];
    float* out = (float*)d_out;

    __half *xh, *y1h, *Wt;
    int* pnbr;
    float *partials, *ss1, *ss2;
    cudaGetSymbolAddress((void**)&xh,       g_xh);
    cudaGetSymbolAddress((void**)&y1h,      g_y1h);
    cudaGetSymbolAddress((void**)&Wt,       g_Wt);
    cudaGetSymbolAddress((void**)&pnbr,     g_pnbr);
    cudaGetSymbolAddress((void**)&partials, g_partials);
    cudaGetSymbolAddress((void**)&ss1,      g_ss1);
    cudaGetSymbolAddress((void**)&ss2,      g_ss2);

    cudaFuncSetAttribute(conv_kernel<__half>, cudaFuncAttributeMaxDynamicSharedMemorySize, SMEM_TOTAL);
    cudaFuncSetAttribute(conv_kernel<float>,  cudaFuncAttributeMaxDynamicSharedMemorySize, SMEM_TOTAL);

    const int convBlocks = (NV + MROWS - 1) / MROWS;           // 1954
    const int cvtBlocks  = (int)(((long)NV * 16) / 256);       // 31250, exact
    const int bnHBlocks  = (int)(((long)NV * 32) / 256);       // 62500, exact
    const int wBlocks    = (2 * KK * 4096 + 255) / 256;
    const int pkBlocks   = (int)(((long)KK * NV + 255) / 256);

    cvt_features_kernel<<<cvtBlocks, 256>>>((const float4*)features, (__half2*)xh);
    cvt_weights_kernel<<<wBlocks, 256>>>(W1, W2, Wt);
    pack_nbr_kernel<<<pkBlocks, 256>>>(nbr, valid, pnbr);

    conv_kernel<__half><<<convBlocks, 256, SMEM_TOTAL>>>(xh, pnbr, Wt, y1h);
    stats_half_kernel<<<512, 256>>>((const __half2*)y1h, partials);
    finalize_stats_kernel<<<1, 64>>>(partials, gamma1, beta1, ss1);
    bn_act_half_kernel<<<bnHBlocks, 256>>>((__half2*)y1h, ss1);

    conv_kernel<float><<<convBlocks, 256, SMEM_TOTAL>>>(y1h, pnbr, Wt + (size_t)KK * 4096, out);
    stats_float_kernel<<<512, 256>>>(out, partials);
    finalize_stats_kernel<<<1, 64>>>(partials, gamma2, beta2, ss2);
    bn_act_float_kernel<<<cvtBlocks, 256>>>(out, ss2, features);
}